// round 1
// baseline (speedup 1.0000x reference)
#include <cuda_runtime.h>
#include <math.h>

#define L_SEQ 4096
#define EDIM  512
#define HDIM  1024
#define G3    3072   // 3*HDIM

// ---------------- scratch (static device globals; no allocation) -------------
__device__ float g_emb[(size_t)L_SEQ * EDIM];          // 8 MB
__device__ float g_gi [(size_t)L_SEQ * G3];            // 50 MB (reused per layer)
__device__ float g_ys [(size_t)L_SEQ * HDIM];          // 16 MB (layer-0 outputs)
__device__ float g_h  [2 * HDIM];                      // double-buffered hidden state
__device__ unsigned g_bar_count;
__device__ unsigned g_bar_gen;

// ---------------- embedding + max-norm --------------------------------------
__global__ void embed_kernel(const int* __restrict__ idx,
                             const float* __restrict__ E,
                             float* __restrict__ emb)
{
    int t = blockIdx.x;                 // token
    int id = idx[t];
    const float4* row = (const float4*)(E + (size_t)id * EDIM);
    float4 v = row[threadIdx.x];        // 128 threads * 4 floats = 512
    float ss = v.x*v.x + v.y*v.y + v.z*v.z + v.w*v.w;
    #pragma unroll
    for (int o = 16; o; o >>= 1) ss += __shfl_xor_sync(0xffffffffu, ss, o);
    __shared__ float red[4];
    int w = threadIdx.x >> 5;
    if ((threadIdx.x & 31) == 0) red[w] = ss;
    __syncthreads();
    float tot = red[0] + red[1] + red[2] + red[3];
    float scale = fminf(1.0f, 1.0f / fmaxf(sqrtf(tot), 1e-7f));
    v.x *= scale; v.y *= scale; v.z *= scale; v.w *= scale;
    ((float4*)(emb + (size_t)t * EDIM))[threadIdx.x] = v;
}

// ---------------- fp32 GEMM: C[M,N] = A[M,K] @ B[N,K]^T + bias[N] -----------
__global__ void __launch_bounds__(256) gemm_tn(const float* __restrict__ A,
                                               const float* __restrict__ B,
                                               const float* __restrict__ bias,
                                               float* __restrict__ C,
                                               int M, int N, int K)
{
    __shared__ float As[16][128];
    __shared__ float Bs[16][136];     // padded row (544B, 16B aligned)

    int tid = threadIdx.x;
    int bm = blockIdx.y * 128;
    int bn = blockIdx.x * 128;
    int tx = tid & 15;
    int ty = tid >> 4;

    float acc[8][8];
    #pragma unroll
    for (int i = 0; i < 8; i++)
        #pragma unroll
        for (int j = 0; j < 8; j++) acc[i][j] = 0.0f;

    const float* Ab = A + (size_t)bm * K;
    const float* Bb = B + (size_t)bn * K;

    for (int k0 = 0; k0 < K; k0 += 16) {
        #pragma unroll
        for (int i = 0; i < 2; i++) {
            int q   = tid + i * 256;   // 0..511
            int row = q >> 2;          // 0..127
            int c4  = q & 3;           // float4 index within 16-k chunk
            float4 a = *(const float4*)(Ab + (size_t)row * K + k0 + c4 * 4);
            As[c4*4+0][row] = a.x; As[c4*4+1][row] = a.y;
            As[c4*4+2][row] = a.z; As[c4*4+3][row] = a.w;
            float4 b = *(const float4*)(Bb + (size_t)row * K + k0 + c4 * 4);
            Bs[c4*4+0][row] = b.x; Bs[c4*4+1][row] = b.y;
            Bs[c4*4+2][row] = b.z; Bs[c4*4+3][row] = b.w;
        }
        __syncthreads();
        #pragma unroll
        for (int k = 0; k < 16; k++) {
            float4 a0 = *(const float4*)&As[k][ty*8];
            float4 a1 = *(const float4*)&As[k][ty*8+4];
            float4 b0 = *(const float4*)&Bs[k][tx*8];
            float4 b1 = *(const float4*)&Bs[k][tx*8+4];
            float av[8] = {a0.x,a0.y,a0.z,a0.w,a1.x,a1.y,a1.z,a1.w};
            float bv[8] = {b0.x,b0.y,b0.z,b0.w,b1.x,b1.y,b1.z,b1.w};
            #pragma unroll
            for (int i = 0; i < 8; i++)
                #pragma unroll
                for (int j = 0; j < 8; j++)
                    acc[i][j] = fmaf(av[i], bv[j], acc[i][j]);
        }
        __syncthreads();
    }

    float bb[8];
    #pragma unroll
    for (int j = 0; j < 8; j++) bb[j] = bias[bn + tx*8 + j];
    #pragma unroll
    for (int i = 0; i < 8; i++) {
        size_t row = (size_t)(bm + ty*8 + i);
        float4 o0 = make_float4(acc[i][0]+bb[0], acc[i][1]+bb[1], acc[i][2]+bb[2], acc[i][3]+bb[3]);
        float4 o1 = make_float4(acc[i][4]+bb[4], acc[i][5]+bb[5], acc[i][6]+bb[6], acc[i][7]+bb[7]);
        *(float4*)(C + row * N + bn + tx*8    ) = o0;
        *(float4*)(C + row * N + bn + tx*8 + 4) = o1;
    }
}

// ---------------- grid barrier (all CTAs co-resident) ------------------------
__device__ __forceinline__ void grid_barrier_dev(unsigned nb)
{
    __syncthreads();
    if (threadIdx.x == 0) {
        __threadfence();
        volatile unsigned* vgen = &g_bar_gen;
        unsigned gen = *vgen;
        if (atomicAdd(&g_bar_count, 1u) == nb - 1u) {
            g_bar_count = 0u;
            __threadfence();
            atomicAdd(&g_bar_gen, 1u);
        } else {
            while (*vgen == gen) { }
        }
        __threadfence();
    }
    __syncthreads();
}

// ---------------- persistent GRU recurrence ----------------------------------
// 128 CTAs x 256 threads. CTA b owns units [b*8, b*8+8); warp w owns unit b*8+w.
// W_hh rows (r,z,n) for the unit live in registers: lane covers k = c*128+lane*4.
__global__ void __launch_bounds__(256, 1) gru_scan(const float* __restrict__ Whh,
                                                   const float* __restrict__ bhh,
                                                   const float* __restrict__ gi,
                                                   float* __restrict__ ys,
                                                   float* __restrict__ hfin,
                                                   float* __restrict__ hfin2,
                                                   int T)
{
    int tid  = threadIdx.x;
    int w    = tid >> 5;
    int lane = tid & 31;
    int b    = blockIdx.x;
    int unit = b * 8 + w;

    const float4* Wr = (const float4*)(Whh + (size_t)unit            * HDIM);
    const float4* Wz = (const float4*)(Whh + (size_t)(HDIM   + unit) * HDIM);
    const float4* Wn = (const float4*)(Whh + (size_t)(2*HDIM + unit) * HDIM);
    float4 wr[8], wz[8], wn[8];
    #pragma unroll
    for (int c = 0; c < 8; c++) {
        wr[c] = Wr[c*32 + lane];
        wz[c] = Wz[c*32 + lane];
        wn[c] = Wn[c*32 + lane];
    }
    float br  = bhh[unit];
    float bz  = bhh[HDIM   + unit];
    float bn_ = bhh[2*HDIM + unit];

    __shared__ __align__(16) float h_s[HDIM];
    __shared__ float gi_s[24];
    volatile float* vh = g_h;
    float h_last = 0.0f;
    unsigned nb = gridDim.x;

    for (int t = 0; t < T; t++) {
        int rbuf = (t & 1) * HDIM;
        int wbuf = ((t + 1) & 1) * HDIM;
        if (tid < 24)
            gi_s[tid] = gi[(size_t)t * G3 + (size_t)(tid >> 3) * HDIM + b*8 + (tid & 7)];
        #pragma unroll
        for (int i = 0; i < 4; i++)
            h_s[tid + i*256] = vh[rbuf + tid + i*256];
        __syncthreads();

        float ar = 0.f, az = 0.f, an = 0.f;
        #pragma unroll
        for (int c = 0; c < 8; c++) {
            float4 h4 = *(const float4*)&h_s[c*128 + lane*4];
            ar = fmaf(wr[c].x,h4.x, fmaf(wr[c].y,h4.y, fmaf(wr[c].z,h4.z, fmaf(wr[c].w,h4.w, ar))));
            az = fmaf(wz[c].x,h4.x, fmaf(wz[c].y,h4.y, fmaf(wz[c].z,h4.z, fmaf(wz[c].w,h4.w, az))));
            an = fmaf(wn[c].x,h4.x, fmaf(wn[c].y,h4.y, fmaf(wn[c].z,h4.z, fmaf(wn[c].w,h4.w, an))));
        }
        #pragma unroll
        for (int o = 16; o; o >>= 1) {
            ar += __shfl_xor_sync(0xffffffffu, ar, o);
            az += __shfl_xor_sync(0xffffffffu, az, o);
            an += __shfl_xor_sync(0xffffffffu, an, o);
        }
        if (lane == 0) {
            float ghr = ar + br, ghz = az + bz, ghn = an + bn_;
            float xr = gi_s[w], xz = gi_s[8 + w], xn = gi_s[16 + w];
            float r = 1.0f / (1.0f + expf(-(xr + ghr)));
            float z = 1.0f / (1.0f + expf(-(xz + ghz)));
            float n = tanhf(xn + r * ghn);
            float hp = h_s[unit];
            float hnw = (1.0f - z) * n + z * hp;
            g_h[wbuf + unit] = hnw;
            if (ys) ys[(size_t)t * HDIM + unit] = hnw;
            h_last = hnw;
        }
        grid_barrier_dev(nb);
    }

    if (lane == 0) {
        hfin[unit] = h_last;
        if (hfin2) hfin2[unit] = h_last;
    }
}

__global__ void zero_h_kernel()
{
    g_h[threadIdx.x]        = 0.0f;
    g_h[1024 + threadIdx.x] = 0.0f;
}

// ---------------- launch -----------------------------------------------------
extern "C" void kernel_launch(void* const* d_in, const int* in_sizes, int n_in,
                              void* d_out, int out_size)
{
    const int*   idx  = (const int*)  d_in[0];
    const float* E    = (const float*)d_in[1];
    const float* Wih0 = (const float*)d_in[2];
    const float* Whh0 = (const float*)d_in[3];
    const float* bih0 = (const float*)d_in[4];
    const float* bhh0 = (const float*)d_in[5];
    const float* Wih1 = (const float*)d_in[6];
    const float* Whh1 = (const float*)d_in[7];
    const float* bih1 = (const float*)d_in[8];
    const float* bhh1 = (const float*)d_in[9];
    float* out = (float*)d_out;

    float *emb, *gi, *ysv;
    cudaGetSymbolAddress((void**)&emb, g_emb);
    cudaGetSymbolAddress((void**)&gi,  g_gi);
    cudaGetSymbolAddress((void**)&ysv, g_ys);

    // 1) embedding + max-norm
    embed_kernel<<<L_SEQ, 128>>>(idx, E, emb);

    // 2) layer-0 input projection: gi = emb @ Wih0^T + bih0
    gemm_tn<<<dim3(G3/128, L_SEQ/128), 256>>>(emb, Wih0, bih0, gi, L_SEQ, G3, EDIM);

    // 3) layer-0 recurrence -> ys1, h1 (h1 -> out[1024:2048])
    zero_h_kernel<<<1, 1024>>>();
    gru_scan<<<128, 256>>>(Whh0, bhh0, gi, ysv, out + HDIM, nullptr, L_SEQ);

    // 4) layer-1 input projection: gi = ys1 @ Wih1^T + bih1
    gemm_tn<<<dim3(G3/128, L_SEQ/128), 256>>>(ysv, Wih1, bih1, gi, L_SEQ, G3, HDIM);

    // 5) layer-1 recurrence -> h2 (h2 -> out[2048:3072] and out[0:1024])
    zero_h_kernel<<<1, 1024>>>();
    gru_scan<<<128, 256>>>(Whh1, bhh1, gi, nullptr, out + 2*HDIM, out, L_SEQ);
}